// round 11
// baseline (speedup 1.0000x reference)
#include <cuda_runtime.h>
#include <cuda_fp16.h>
#include <math.h>

#define BB 16
#define TENC 512
#define DENC 512
#define NMEL 80
#define FRAME 240
#define TSTEPS 200
#define NFRAMES 199
#define PRE 256
#define ARNN 1024
#define ADIM 128
#define GRID 148
#define NTHR 256
#define NUNITS 415
#define WSTH 72                               // halves per weight row in smem (144B)
#define SMEM_FLOATS (4096 + 2 * 256 * WSTH / 2)

__device__ float g_xraw[NFRAMES * BB * FRAME];
__device__ float g_h1[NFRAMES * BB * PRE];
__device__ float g_preT[TSTEPS * PRE * BB];     // [t][f][b]
__device__ float g_pm[BB * TENC * ADIM];
__device__ float g_procloc[BB * TENC * ADIM];
__device__ float g_haT[ARNN * BB];              // [j][b]
__device__ float g_caT[ARNN * BB];
__device__ float g_hdT[ARNN * BB];
__device__ float g_cdT[ARNN * BB];
__device__ float g_ctx[2 * DENC * BB];          // [parity][d][b]
__device__ float g_w[BB * TENC];
__device__ float g_wcum[BB * TENC];
__device__ float g_pA[8 * BB * 4096];           // [slot][b][row]
__device__ float g_pD[10 * BB * 4096];
__device__ int   g_wflag[BB * 32];
__device__ unsigned g_qcnt[TSTEPS];
__device__ __align__(128) unsigned g_barA[32];
__device__ __align__(128) unsigned g_barB[32];

// fp16 copies (converted once per launch in k_prep)
__device__ __align__(16) __half h_awih[4096 * 768];
__device__ __align__(16) __half h_awhh[4096 * 1024];
__device__ __align__(16) __half h_dwih[4096 * 1536];
__device__ __align__(16) __half h_dwhh[4096 * 1024];
__device__ __align__(16) __half h_mem[BB * TENC * DENC];

__device__ __forceinline__ float sigf(float x) { return 1.f / (1.f + expf(-x)); }
__device__ __forceinline__ float tanh_fast(float x) {
    float y; asm("tanh.approx.f32 %0, %1;" : "=f"(y) : "f"(x)); return y;
}

__device__ __forceinline__ void cp16cg(__half* s, const __half* g) {
    unsigned ss = (unsigned)__cvta_generic_to_shared(s);
    asm volatile("cp.async.cg.shared.global [%0], [%1], 16;" :: "r"(ss), "l"(g));
}
__device__ __forceinline__ void cp_commit() { asm volatile("cp.async.commit_group;"); }
__device__ __forceinline__ void cp_wait0() { asm volatile("cp.async.wait_group 0;"); }
__device__ __forceinline__ void cp_wait1() { asm volatile("cp.async.wait_group 1;"); }

__device__ __forceinline__ void gsync(unsigned ph) {
    __threadfence();
    __syncthreads();
    if (threadIdx.x == 0) {
        if (atomicAdd(&g_barA[0], 1u) == GRID - 1) {
            g_barA[0] = 0;
            __threadfence();
            *(volatile unsigned*)&g_barB[0] = ph;
        } else {
            while (*(volatile unsigned*)&g_barB[0] != ph) __nanosleep(32);
            __threadfence();
        }
    }
    __syncthreads();
}

// ---------------- launch 1: init + gather + fp16 conversions ----------------
__global__ void k_prep(const float* __restrict__ din,
                       const float* __restrict__ aw_ih, const float* __restrict__ aw_hh,
                       const float* __restrict__ dw_ih, const float* __restrict__ dw_hh,
                       const float* __restrict__ memory) {
    int i0 = blockIdx.x * 256 + threadIdx.x;
    int st = gridDim.x * 256;
    if (i0 == 0) { g_barA[0] = 0; g_barB[0] = 0; }
    for (int k = i0; k < TSTEPS; k += st) g_qcnt[k] = 0;
    for (int k = i0; k < ARNN * BB; k += st) { g_haT[k]=0.f; g_caT[k]=0.f; g_hdT[k]=0.f; g_cdT[k]=0.f; }
    for (int k = i0; k < 2 * DENC * BB; k += st) g_ctx[k] = 0.f;
    for (int k = i0; k < BB * TENC; k += st) { g_w[k] = 0.f; g_wcum[k] = 0.f; }
    for (int k = i0; k < PRE * BB; k += st) g_preT[k] = 0.f;
    for (int k = i0; k < BB * 32; k += st) g_wflag[k] = 0;
    for (int k = i0; k < 8 * BB * 4096; k += st) g_pA[k] = 0.f;
    for (int k = i0; k < BB * TENC * ADIM; k += st) g_procloc[k] = 0.f;
    for (int idx = i0; idx < NFRAMES * BB * FRAME; idx += st) {
        int j = idx % FRAME, m = idx / FRAME;
        int b = m % BB, d = m / BB;
        int flat = d * FRAME + j;
        g_xraw[idx] = din[(b * NMEL + flat % NMEL) * 600 + flat / NMEL];
    }
    for (int k = i0; k < 4096 * 768; k += st) h_awih[k] = __float2half(aw_ih[k]);
    for (int k = i0; k < 4096 * 1024; k += st) h_awhh[k] = __float2half(aw_hh[k]);
    for (int k = i0; k < 4096 * 1536; k += st) h_dwih[k] = __float2half(dw_ih[k]);
    for (int k = i0; k < 4096 * 1024; k += st) h_dwhh[k] = __float2half(dw_hh[k]);
    for (int k = i0; k < BB * TENC * DENC; k += st) h_mem[k] = __float2half(memory[k]);
}

// ---------------- prologue SGEMM tile (shared by launches 2 and 3) ----------------
__device__ void sgemm_tile(float* As, float* Bs,
                           const float* __restrict__ A, const float* __restrict__ Bw,
                           float* __restrict__ C, int M, int N, int K, int relu, int mode,
                           int m0, int n0) {
    int tx = threadIdx.x, tr = tx >> 4, tc = tx & 15;
    float acc[4][4] = {};
    for (int k0 = 0; k0 < K; k0 += 16) {
        for (int i = tx; i < 1024; i += 256) {
            int mm = i >> 4, kk = i & 15;
            int m = m0 + mm, k = k0 + kk;
            As[kk * 68 + mm] = (m < M) ? A[(size_t)m * K + k] : 0.f;
            int n = n0 + mm;
            Bs[kk * 68 + mm] = (n < N) ? Bw[(size_t)n * K + k] : 0.f;
        }
        __syncthreads();
#pragma unroll
        for (int kk = 0; kk < 16; kk++) {
            float4 a4 = *(const float4*)&As[kk * 68 + tr * 4];
            float4 b4 = *(const float4*)&Bs[kk * 68 + tc * 4];
            float a_[4] = {a4.x, a4.y, a4.z, a4.w};
            float b_[4] = {b4.x, b4.y, b4.z, b4.w};
#pragma unroll
            for (int r = 0; r < 4; r++)
#pragma unroll
                for (int c = 0; c < 4; c++) acc[r][c] += a_[r] * b_[c];
        }
        __syncthreads();
    }
    for (int r = 0; r < 4; r++)
        for (int c = 0; c < 4; c++) {
            int m = m0 + tr * 4 + r, n = n0 + tc * 4 + c;
            if (m < M && n < N) {
                float v = acc[r][c];
                if (relu) v = fmaxf(v, 0.f);
                if (mode == 0) C[(size_t)m * N + n] = v;
                else C[(((m >> 4) + 1) * PRE + n) * BB + (m & 15)] = v;
            }
        }
}

// launch 2: prenet layer 1
__global__ void k_sgemm(const float* __restrict__ A, const float* __restrict__ Bw,
                        float* __restrict__ C, int M, int N, int K, int relu, int mode) {
    __shared__ float As[16 * 68];
    __shared__ float Bs[16 * 68];
    sgemm_tile(As, Bs, A, Bw, C, M, N, K, relu, mode, blockIdx.x * 64, blockIdx.y * 64);
}

// launch 3: prenet layer 2 (blocks 0..199) || processed_memory (blocks 200..455)
__global__ void k_sgemm2(const float* __restrict__ pw2, const float* __restrict__ memory,
                         const float* __restrict__ Wm) {
    __shared__ float As[16 * 68];
    __shared__ float Bs[16 * 68];
    if (blockIdx.x < 200) {
        int bx = blockIdx.x % 50, by = blockIdx.x / 50;
        sgemm_tile(As, Bs, g_h1, pw2, g_preT, NFRAMES * BB, PRE, PRE, 1, 1, bx * 64, by * 64);
    } else {
        int v = blockIdx.x - 200;
        int bx = v % 128, by = v / 128;
        sgemm_tile(As, Bs, memory, Wm, g_pm, BB * TENC, ADIM, DENC, 0, 0, bx * 64, by * 64);
    }
}

__device__ __forceinline__ void stage(float* dst, const float* src, int nfloats, int tid) {
    const float4* s4 = (const float4*)src;
    float4* d4 = (float4*)dst;
    int n4 = nfloats >> 2;
    for (int i = tid; i < n4; i += NTHR) d4[i] = __ldcg(s4 + i);
}

__device__ __forceinline__ void issue_chunk(__half* wbufs, const __half* wA, int strA, int lenA,
        const __half* wB, int strB, int rowbase, int kg, int buf, int lrow, int lkh) {
    const __half* ws; int wst; int ko;
    if (kg < lenA) { ws = wA; wst = strA; ko = kg; } else { ws = wB; wst = strB; ko = kg - lenA; }
    __half* dst = wbufs + buf * (256 * WSTH);
#pragma unroll
    for (int i = 0; i < 8; i++) {
        int row = lrow + i * 32;
        cp16cg(dst + row * WSTH + lkh, ws + (size_t)(rowbase + row) * wst + ko + lkh);
    }
    cp_commit();
}

// ---- cp.async gate unit: 256 rows x 256 K, 64-wide double-buffered chunks ----
__device__ void gate_unit2(float* act, __half* wbufs,
    const __half* wA, int strA, int lenA, const __half* wB, int strB,
    const float* a0, int l0, const float* a1, int l1, const float* a2, int l2,
    float* part, int slot, int rowbase, int kbeg, int tid)
{
    int kend = kbeg + 256;
    {
        int o0s = max(kbeg, 0), o0e = min(kend, l0);
        if (o0e > o0s) stage(act + (o0s - kbeg) * BB, a0 + o0s * BB, (o0e - o0s) * BB, tid);
        int s1s = l0, s1e = l0 + l1;
        int o1s = max(kbeg, s1s), o1e = min(kend, s1e);
        if (l1 && o1e > o1s) stage(act + (o1s - kbeg) * BB, a1 + (o1s - s1s) * BB, (o1e - o1s) * BB, tid);
        int s2s = s1e, s2e = s1e + l2;
        int o2s = max(kbeg, s2s), o2e = min(kend, s2e);
        if (l2 && o2e > o2s) stage(act + (o2s - kbeg) * BB, a2 + (o2s - s2s) * BB, (o2e - o2s) * BB, tid);
    }
    int lrow = tid >> 3, lkh = (tid & 7) * 8;
    issue_chunk(wbufs, wA, strA, lenA, wB, strB, rowbase, kbeg, 0, lrow, lkh);
    int rg = tid >> 2, b4 = (tid & 3) * 4;
    float acc[4][4] = {};
#pragma unroll
    for (int c = 0; c < 4; c++) {
        if (c + 1 < 4) {
            issue_chunk(wbufs, wA, strA, lenA, wB, strB, rowbase, kbeg + (c + 1) * 64, (c + 1) & 1, lrow, lkh);
            cp_wait1();
        } else {
            cp_wait0();
        }
        __syncthreads();
        const __half* wb = wbufs + (c & 1) * (256 * WSTH);
        const float* ac = act + c * 64 * BB;
#pragma unroll 8
        for (int l = 0; l < 64; l += 4) {
            float4 av0 = *(const float4*)&ac[(l + 0) * BB + b4];
            float4 av1 = *(const float4*)&ac[(l + 1) * BB + b4];
            float4 av2 = *(const float4*)&ac[(l + 2) * BB + b4];
            float4 av3 = *(const float4*)&ac[(l + 3) * BB + b4];
#pragma unroll
            for (int m = 0; m < 4; m++) {
                uint2 wr = *(const uint2*)(wb + (rg + (m << 6)) * WSTH + l);
                float2 w01 = __half22float2(*reinterpret_cast<__half2*>(&wr.x));
                float2 w23 = __half22float2(*reinterpret_cast<__half2*>(&wr.y));
                acc[m][0] += w01.x * av0.x + w01.y * av1.x + w23.x * av2.x + w23.y * av3.x;
                acc[m][1] += w01.x * av0.y + w01.y * av1.y + w23.x * av2.y + w23.y * av3.y;
                acc[m][2] += w01.x * av0.z + w01.y * av1.z + w23.x * av2.z + w23.y * av3.z;
                acc[m][3] += w01.x * av0.w + w01.y * av1.w + w23.x * av2.w + w23.y * av3.w;
            }
        }
        __syncthreads();
    }
#pragma unroll
    for (int m = 0; m < 4; m++)
#pragma unroll
        for (int cc = 0; cc < 4; cc++)
            part[(size_t)((slot * BB + b4 + cc) << 12) + rowbase + rg + (m << 6)] = acc[m][cc];
    __syncthreads();
}

__device__ void loc64(int b, int e, const float* __restrict__ lw,
                      const float* __restrict__ ld_, float* sbuf, int tid) {
    float* win = sbuf;
    float* locs = sbuf + 192;
    int t0 = e * 64;
    if (tid < 192) {
        int ch = tid / 96, idx = tid % 96;
        int tt = t0 - 15 + idx;
        bool ok = (idx < 94) && (tt >= 0) && (tt < TENC);
        const float* src = ch ? g_wcum : g_w;
        win[ch * 96 + idx] = ok ? __ldcg(&src[b * TENC + tt]) : 0.f;
    }
    __syncthreads();
    for (int i = tid; i < 2048; i += NTHR) {
        int c = i >> 6, tt = i & 63;
        float acc = 0.f;
#pragma unroll
        for (int ch = 0; ch < 2; ch++)
#pragma unroll
            for (int kk = 0; kk < 31; kk++)
                acc += win[ch * 96 + tt + kk] * lw[c * 62 + ch * 31 + kk];
        locs[c * 64 + tt] = acc;
    }
    __syncthreads();
    int f = tid & 127, tg = tid >> 7;
    float ldr[32];
#pragma unroll
    for (int c = 0; c < 32; c++) ldr[c] = ld_[f * 32 + c];
    for (int tt = tg * 32; tt < tg * 32 + 32; tt++) {
        float acc = 0.f;
#pragma unroll
        for (int c = 0; c < 32; c++) acc += locs[c * 64 + tt] * ldr[c];
        g_procloc[((size_t)(b * TENC + t0 + tt)) * ADIM + f] = acc;
    }
    __syncthreads();
}

__device__ void proj_unit2(int t, int v, const float* __restrict__ pw,
                           const float* __restrict__ pb, float* __restrict__ out_mel,
                           float* act, int tid) {
    int r = v * 16 + (tid >> 4), b = tid & 15;
    const float* wr = pw + (size_t)r * 1536;
    const float* cx = g_ctx + ((t - 1) & 1) * DENC * BB;
    float acc = 0.f;
    for (int ch = 0; ch < 6; ch++) {
        const float* src = (ch < 4) ? g_hdT + ch * 256 * BB : cx + (ch - 4) * 256 * BB;
        stage(act, src, 256 * BB, tid);
        __syncthreads();
        const float* w = wr + ch * 256;
#pragma unroll 8
        for (int k = 0; k < 256; k += 4) {
            float4 wv = *(const float4*)(w + k);
            acc += wv.x * act[(k + 0) * BB + b] + wv.y * act[(k + 1) * BB + b] +
                   wv.z * act[(k + 2) * BB + b] + wv.w * act[(k + 3) * BB + b];
        }
        __syncthreads();
    }
    acc += pb[r];
    int flat = (t - 1) * FRAME + r;
    out_mel[(size_t)b * (NMEL * 600) + (flat % NMEL) * 600 + flat / NMEL] = acc;
}

// ---------------- launch 4: the persistent megakernel ----------------
__global__ void __launch_bounds__(NTHR) k_mega(
    const int* __restrict__ mlen,
    const float* __restrict__ ab_ih, const float* __restrict__ ab_hh,
    const float* __restrict__ db_ih, const float* __restrict__ db_hh,
    const float* __restrict__ Wq, const float* __restrict__ v_att,
    const float* __restrict__ lconv, const float* __restrict__ ldense,
    const float* __restrict__ proj_w, const float* __restrict__ proj_b,
    float* __restrict__ out_mel, float* __restrict__ out_align)
{
    extern __shared__ float dsm[];
    float* act = dsm;                               // [4096]
    __half* wbufs = (__half*)(dsm + 4096);          // [2][256*WSTH]
    float* sh = dsm;                                // Phase A alias
    __shared__ int sh_u;
    int cta = blockIdx.x, tid = threadIdx.x;
    unsigned ph = 0;

    for (int t = 0; t <= TSTEPS; t++) {
        // =========== Phase A ===========
        if (cta < 16 && t < TSTEPS) {
            int b = cta;
            float* s_ha = sh;
            for (int j = tid; j < ARNN; j += NTHR) {
                float g[4];
#pragma unroll
                for (int gi = 0; gi < 4; gi++) {
                    int row = gi * 1024 + j;
                    float s = ab_ih[row] + ab_hh[row];
#pragma unroll
                    for (int sl = 0; sl < 7; sl++)
                        s += __ldcg(&g_pA[(size_t)((sl * BB + b) << 12) + row]);
                    g[gi] = s;
                }
                float c = sigf(g[1]) * __ldcg(&g_caT[j * BB + b]) + sigf(g[0]) * tanhf(g[2]);
                float h = sigf(g[3]) * tanhf(c);
                g_caT[j * BB + b] = c;
                g_haT[j * BB + b] = h;
                s_ha[j] = h;
            }
            __syncthreads();
            {
                int f = tid & 127, hf = tid >> 7;
                const float* wr = Wq + (size_t)f * ARNN + hf * 512;
                const float* ha = s_ha + hf * 512;
                float acc = 0.f;
#pragma unroll 4
                for (int k = 0; k < 512; k += 4) {
                    float4 wv = *(const float4*)(wr + k);
                    acc += wv.x * ha[k] + wv.y * ha[k + 1] + wv.z * ha[k + 2] + wv.w * ha[k + 3];
                }
                sh[1024 + tid] = acc;
            }
            __syncthreads();
            if (tid < 128) {
                sh[1280 + tid] = sh[1024 + tid] + sh[1152 + tid];
                sh[1408 + tid] = v_att[tid];
            }
            __syncthreads();
            int L = mlen[b];
            float ev[2];
#pragma unroll
            for (int it = 0; it < 2; it++) {
                int tt = tid + it * 256;
                const float* pl = &g_procloc[((size_t)b * TENC + tt) * ADIM];
                const float* pv = &g_pm[((size_t)b * TENC + tt) * ADIM];
                float acc = 0.f;
#pragma unroll 4
                for (int f = 0; f < ADIM; f += 4) {
                    float4 a = __ldcg((const float4*)(pl + f));
                    float4 p = __ldg((const float4*)(pv + f));
                    acc += sh[1408 + f + 0] * tanh_fast(sh[1280 + f + 0] + a.x + p.x);
                    acc += sh[1408 + f + 1] * tanh_fast(sh[1280 + f + 1] + a.y + p.y);
                    acc += sh[1408 + f + 2] * tanh_fast(sh[1280 + f + 2] + a.z + p.z);
                    acc += sh[1408 + f + 3] * tanh_fast(sh[1280 + f + 3] + a.w + p.w);
                }
                ev[it] = (tt >= L) ? -1e9f : acc;
            }
            float* red = sh + 1536;
            red[tid] = fmaxf(ev[0], ev[1]);
            __syncthreads();
            for (int s = 128; s > 0; s >>= 1) {
                if (tid < s) red[tid] = fmaxf(red[tid], red[tid + s]);
                __syncthreads();
            }
            float mx = red[0];
            __syncthreads();
            float ex0 = expf(ev[0] - mx), ex1 = expf(ev[1] - mx);
            red[tid] = ex0 + ex1;
            __syncthreads();
            for (int s = 128; s > 0; s >>= 1) {
                if (tid < s) red[tid] += red[tid + s];
                __syncthreads();
            }
            float inv = 1.f / red[0];
            {
                float wv = ex0 * inv;
                g_w[b * TENC + tid] = wv;
                g_wcum[b * TENC + tid] = __ldcg(&g_wcum[b * TENC + tid]) + wv;
                out_align[((size_t)b * TSTEPS + t) * TENC + tid] = wv;
                wv = ex1 * inv;
                g_w[b * TENC + tid + 256] = wv;
                g_wcum[b * TENC + tid + 256] = __ldcg(&g_wcum[b * TENC + tid + 256]) + wv;
                out_align[((size_t)b * TSTEPS + t) * TENC + tid + 256] = wv;
            }
            __syncthreads();
            __threadfence();
            if (tid == 0) *(volatile int*)&g_wflag[b * 32] = t + 1;
        } else if (cta >= 16 && cta < 80 && t < TSTEPS) {
            int v = cta - 16, b = v >> 2, d0 = (v & 3) * 128;
            if (tid == 0) {
                while (*(volatile int*)&g_wflag[b * 32] != t + 1) __nanosleep(32);
            }
            __syncthreads();
            for (int i = tid; i < TENC; i += NTHR) sh[i] = __ldcg(&g_w[b * TENC + i]);
            __syncthreads();
            int dp = (tid & 63) * 2, hf = tid >> 6;
            const __half* mb = h_mem + ((size_t)b * TENC + hf * 128) * DENC + d0 + dp;
            float a0 = 0.f, a1 = 0.f;
#pragma unroll 8
            for (int tt = 0; tt < 128; tt++) {
                float2 f2 = __half22float2(__ldg((const __half2*)&mb[(size_t)tt * DENC]));
                float wv = sh[hf * 128 + tt];
                a0 += wv * f2.x;
                a1 += wv * f2.y;
            }
            sh[512 + hf * 128 + dp] = a0;
            sh[512 + hf * 128 + dp + 1] = a1;
            __syncthreads();
            if (tid < 128) {
                float s = sh[512 + tid] + sh[640 + tid] + sh[768 + tid] + sh[896 + tid];
                g_ctx[(t & 1) * DENC * BB + (d0 + tid) * BB + b] = s;
            }
        } else if (cta >= 80 && cta < 144 && t > 0) {
            int v = cta - 80, b = v >> 2, j = (v & 3) * 256 + tid;
            float g[4];
#pragma unroll
            for (int gi = 0; gi < 4; gi++) {
                int row = gi * 1024 + j;
                float s = db_ih[row] + db_hh[row];
#pragma unroll
                for (int sl = 0; sl < 10; sl++)
                    s += __ldcg(&g_pD[(size_t)((sl * BB + b) << 12) + row]);
                g[gi] = s;
            }
            float c = sigf(g[1]) * __ldcg(&g_cdT[j * BB + b]) + sigf(g[0]) * tanhf(g[2]);
            float h = sigf(g[3]) * tanhf(c);
            g_cdT[j * BB + b] = c;
            g_hdT[j * BB + b] = h;
        }
        gsync(++ph);
        if (t == TSTEPS) break;

        // =========== Phase B: dynamic work queue ===========
        const float* ctx_t = g_ctx + (t & 1) * DENC * BB;
        for (;;) {
            if (tid == 0) sh_u = (int)atomicAdd(&g_qcnt[t], 1u);
            __syncthreads();
            int u = sh_u;
            __syncthreads();
            if (u >= NUNITS) break;
            if (u < 160) {
                int rc = u / 10, kc = u % 10;
                gate_unit2(act, wbufs,
                           h_dwih, 1536, 1536, h_dwhh, 1024,
                           g_haT, 1024, ctx_t, 512, g_hdT, 1024,
                           g_pD, kc, rc * 256, kc * 256, tid);
            } else if (u < 272) {
                if (t < TSTEPS - 1) {
                    int v = u - 160, rc = v / 7, kc = v % 7;
                    gate_unit2(act, wbufs,
                               h_awih, 768, 768, h_awhh, 1024,
                               g_preT + (size_t)(t + 1) * PRE * BB, 256, ctx_t, 512, g_haT, 1024,
                               g_pA, kc, rc * 256, kc * 256, tid);
                }
            } else if (u < 400) {
                if (t < TSTEPS - 1) {
                    int v = u - 272;
                    loc64(v >> 3, v & 7, lconv, ldense, act, tid);
                }
            } else {
                if (t > 0) proj_unit2(t, u - 400, proj_w, proj_b, out_mel, act, tid);
            }
        }
        gsync(++ph);
    }

    if (cta < 15) proj_unit2(TSTEPS, cta, proj_w, proj_b, out_mel, act, tid);
}

extern "C" void kernel_launch(void* const* d_in, const int* in_sizes, int n_in,
                              void* d_out, int out_size) {
    const float* memory = (const float*)d_in[0];
    const float* dec_in = (const float*)d_in[1];
    const int*   mlen   = (const int*)d_in[2];
    const float* pw1    = (const float*)d_in[3];
    const float* pw2    = (const float*)d_in[4];
    const float* aw_ih  = (const float*)d_in[5];
    const float* aw_hh  = (const float*)d_in[6];
    const float* ab_ih  = (const float*)d_in[7];
    const float* ab_hh  = (const float*)d_in[8];
    const float* dw_ih  = (const float*)d_in[9];
    const float* dw_hh  = (const float*)d_in[10];
    const float* db_ih  = (const float*)d_in[11];
    const float* db_hh  = (const float*)d_in[12];
    const float* Wq     = (const float*)d_in[13];
    const float* Wm     = (const float*)d_in[14];
    const float* v_att  = (const float*)d_in[15];
    const float* lconv  = (const float*)d_in[16];
    const float* ldense = (const float*)d_in[17];
    const float* proj_w = (const float*)d_in[18];
    const float* proj_b = (const float*)d_in[19];

    float* out = (float*)d_out;
    float* align_out = out + (size_t)BB * NMEL * 600;

    float *s_xraw, *s_h1;
    cudaGetSymbolAddress((void**)&s_xraw, g_xraw);
    cudaGetSymbolAddress((void**)&s_h1, g_h1);

    static int smem_set = 0;
    int smem_bytes = SMEM_FLOATS * 4;
    if (!smem_set) {
        cudaFuncSetAttribute(k_mega, cudaFuncAttributeMaxDynamicSharedMemorySize, smem_bytes);
        smem_set = 1;
    }

    // launch 1: init + gather + fp16 conversions
    k_prep<<<2048, 256>>>(dec_in, aw_ih, aw_hh, dw_ih, dw_hh, memory);
    // launch 2: prenet layer 1
    k_sgemm<<<dim3(50, 4), 256>>>(s_xraw, pw1, s_h1, NFRAMES * BB, PRE, FRAME, 1, 0);
    // launch 3: prenet layer 2 || processed_memory
    k_sgemm2<<<456, 256>>>(pw2, memory, Wm);
    // launch 4: megakernel (ncu -s 5 -c 1 captures this one)
    k_mega<<<GRID, NTHR, smem_bytes>>>(mlen,
                           ab_ih, ab_hh, db_ih, db_hh,
                           Wq, v_att, lconv, ldense, proj_w, proj_b,
                           out, align_out);
}

// round 12
// speedup vs baseline: 1.0272x; 1.0272x over previous
#include <cuda_runtime.h>
#include <cuda_fp16.h>
#include <math.h>

#define BB 16
#define TENC 512
#define DENC 512
#define NMEL 80
#define FRAME 240
#define TSTEPS 200
#define NFRAMES 199
#define PRE 256
#define ARNN 1024
#define ADIM 128
#define GRID 148
#define NTHR 512
#define NUNITS 415
#define WSTH 72
#define SMEM_FLOATS (4096 + 2 * 256 * WSTH / 2)

__device__ float g_xraw[NFRAMES * BB * FRAME];
__device__ float g_h1[NFRAMES * BB * PRE];
__device__ float g_preT[TSTEPS * PRE * BB];     // [t][f][b]
__device__ float g_pm[BB * TENC * ADIM];
__device__ float g_procloc[BB * TENC * ADIM];
__device__ float g_haT[ARNN * BB];              // [j][b]
__device__ float g_caT[ARNN * BB];
__device__ float g_hdT[ARNN * BB];
__device__ float g_cdT[ARNN * BB];
__device__ float g_ctx[2 * DENC * BB];          // [parity][d][b]
__device__ float g_w[BB * TENC];
__device__ float g_wcum[BB * TENC];
__device__ float g_pA[8 * BB * 4096];           // [slot][b][row]
__device__ float g_pD[10 * BB * 4096];
__device__ int   g_wflag[BB * 32];
__device__ unsigned g_qcnt[TSTEPS];
__device__ __align__(128) unsigned g_barA[32];
__device__ __align__(128) unsigned g_barB[32];

__device__ __align__(16) __half h_awih[4096 * 768];
__device__ __align__(16) __half h_awhh[4096 * 1024];
__device__ __align__(16) __half h_dwih[4096 * 1536];
__device__ __align__(16) __half h_dwhh[4096 * 1024];
__device__ __align__(16) __half h_mem[BB * TENC * DENC];

__device__ __forceinline__ float sigf(float x) { return 1.f / (1.f + expf(-x)); }
__device__ __forceinline__ float tanh_fast(float x) {
    float y; asm("tanh.approx.f32 %0, %1;" : "=f"(y) : "f"(x)); return y;
}

__device__ __forceinline__ void cp16cg(__half* s, const __half* g) {
    unsigned ss = (unsigned)__cvta_generic_to_shared(s);
    asm volatile("cp.async.cg.shared.global [%0], [%1], 16;" :: "r"(ss), "l"(g));
}
__device__ __forceinline__ void cp_commit() { asm volatile("cp.async.commit_group;"); }
__device__ __forceinline__ void cp_wait0() { asm volatile("cp.async.wait_group 0;"); }
__device__ __forceinline__ void cp_wait1() { asm volatile("cp.async.wait_group 1;"); }

__device__ __forceinline__ void gsync(unsigned ph) {
    __threadfence();
    __syncthreads();
    if (threadIdx.x == 0) {
        if (atomicAdd(&g_barA[0], 1u) == GRID - 1) {
            g_barA[0] = 0;
            __threadfence();
            *(volatile unsigned*)&g_barB[0] = ph;
        } else {
            while (*(volatile unsigned*)&g_barB[0] != ph) __nanosleep(32);
            __threadfence();
        }
    }
    __syncthreads();
}

// ---------------- launch 1: init + gather + fp16 conversions ----------------
__global__ void k_prep(const float* __restrict__ din,
                       const float* __restrict__ aw_ih, const float* __restrict__ aw_hh,
                       const float* __restrict__ dw_ih, const float* __restrict__ dw_hh,
                       const float* __restrict__ memory) {
    int i0 = blockIdx.x * 256 + threadIdx.x;
    int st = gridDim.x * 256;
    if (i0 == 0) { g_barA[0] = 0; g_barB[0] = 0; }
    for (int k = i0; k < TSTEPS; k += st) g_qcnt[k] = 0;
    for (int k = i0; k < ARNN * BB; k += st) { g_haT[k]=0.f; g_caT[k]=0.f; g_hdT[k]=0.f; g_cdT[k]=0.f; }
    for (int k = i0; k < 2 * DENC * BB; k += st) g_ctx[k] = 0.f;
    for (int k = i0; k < BB * TENC; k += st) { g_w[k] = 0.f; g_wcum[k] = 0.f; }
    for (int k = i0; k < PRE * BB; k += st) g_preT[k] = 0.f;
    for (int k = i0; k < BB * 32; k += st) g_wflag[k] = 0;
    for (int k = i0; k < 8 * BB * 4096; k += st) g_pA[k] = 0.f;
    for (int k = i0; k < BB * TENC * ADIM; k += st) g_procloc[k] = 0.f;
    for (int idx = i0; idx < NFRAMES * BB * FRAME; idx += st) {
        int j = idx % FRAME, m = idx / FRAME;
        int b = m % BB, d = m / BB;
        int flat = d * FRAME + j;
        g_xraw[idx] = din[(b * NMEL + flat % NMEL) * 600 + flat / NMEL];
    }
    for (int k = i0; k < 4096 * 768; k += st) h_awih[k] = __float2half(aw_ih[k]);
    for (int k = i0; k < 4096 * 1024; k += st) h_awhh[k] = __float2half(aw_hh[k]);
    for (int k = i0; k < 4096 * 1536; k += st) h_dwih[k] = __float2half(dw_ih[k]);
    for (int k = i0; k < 4096 * 1024; k += st) h_dwhh[k] = __float2half(dw_hh[k]);
    for (int k = i0; k < BB * TENC * DENC; k += st) h_mem[k] = __float2half(memory[k]);
}

// ---------------- prologue SGEMM ----------------
__device__ void sgemm_tile(float* As, float* Bs,
                           const float* __restrict__ A, const float* __restrict__ Bw,
                           float* __restrict__ C, int M, int N, int K, int relu, int mode,
                           int m0, int n0) {
    int tx = threadIdx.x, tr = tx >> 4, tc = tx & 15;
    float acc[4][4] = {};
    for (int k0 = 0; k0 < K; k0 += 16) {
        for (int i = tx; i < 1024; i += 256) {
            int mm = i >> 4, kk = i & 15;
            int m = m0 + mm, k = k0 + kk;
            As[kk * 68 + mm] = (m < M) ? A[(size_t)m * K + k] : 0.f;
            int n = n0 + mm;
            Bs[kk * 68 + mm] = (n < N) ? Bw[(size_t)n * K + k] : 0.f;
        }
        __syncthreads();
#pragma unroll
        for (int kk = 0; kk < 16; kk++) {
            float4 a4 = *(const float4*)&As[kk * 68 + tr * 4];
            float4 b4 = *(const float4*)&Bs[kk * 68 + tc * 4];
            float a_[4] = {a4.x, a4.y, a4.z, a4.w};
            float b_[4] = {b4.x, b4.y, b4.z, b4.w};
#pragma unroll
            for (int r = 0; r < 4; r++)
#pragma unroll
                for (int c = 0; c < 4; c++) acc[r][c] += a_[r] * b_[c];
        }
        __syncthreads();
    }
    for (int r = 0; r < 4; r++)
        for (int c = 0; c < 4; c++) {
            int m = m0 + tr * 4 + r, n = n0 + tc * 4 + c;
            if (m < M && n < N) {
                float v = acc[r][c];
                if (relu) v = fmaxf(v, 0.f);
                if (mode == 0) C[(size_t)m * N + n] = v;
                else C[(((m >> 4) + 1) * PRE + n) * BB + (m & 15)] = v;
            }
        }
}

__global__ void k_sgemm(const float* __restrict__ A, const float* __restrict__ Bw,
                        float* __restrict__ C, int M, int N, int K, int relu, int mode) {
    __shared__ float As[16 * 68];
    __shared__ float Bs[16 * 68];
    sgemm_tile(As, Bs, A, Bw, C, M, N, K, relu, mode, blockIdx.x * 64, blockIdx.y * 64);
}

__global__ void k_sgemm2(const float* __restrict__ pw2, const float* __restrict__ memory,
                         const float* __restrict__ Wm) {
    __shared__ float As[16 * 68];
    __shared__ float Bs[16 * 68];
    if (blockIdx.x < 200) {
        int bx = blockIdx.x % 50, by = blockIdx.x / 50;
        sgemm_tile(As, Bs, g_h1, pw2, g_preT, NFRAMES * BB, PRE, PRE, 1, 1, bx * 64, by * 64);
    } else {
        int v = blockIdx.x - 200;
        int bx = v % 128, by = v / 128;
        sgemm_tile(As, Bs, memory, Wm, g_pm, BB * TENC, ADIM, DENC, 0, 0, bx * 64, by * 64);
    }
}

__device__ __forceinline__ void stage(float* dst, const float* src, int nfloats, int tid) {
    const float4* s4 = (const float4*)src;
    float4* d4 = (float4*)dst;
    int n4 = nfloats >> 2;
    for (int i = tid; i < n4; i += NTHR) d4[i] = __ldcg(s4 + i);
}

__device__ __forceinline__ void issue_chunk(__half* wbufs, const __half* wA, int strA, int lenA,
        const __half* wB, int strB, int rowbase, int kg, int buf, int lrow, int lkh) {
    const __half* ws; int wst; int ko;
    if (kg < lenA) { ws = wA; wst = strA; ko = kg; } else { ws = wB; wst = strB; ko = kg - lenA; }
    __half* dst = wbufs + buf * (256 * WSTH);
#pragma unroll
    for (int i = 0; i < 4; i++) {
        int row = lrow + i * 64;
        cp16cg(dst + row * WSTH + lkh, ws + (size_t)(rowbase + row) * wst + ko + lkh);
    }
    cp_commit();
}

// ---- gate unit: 512 threads, 256 rows x 256 K, 2 rows/thread ----
__device__ void gate_unit2(float* act, __half* wbufs,
    const __half* wA, int strA, int lenA, const __half* wB, int strB,
    const float* a0, int l0, const float* a1, int l1, const float* a2, int l2,
    float* part, int slot, int rowbase, int kbeg, int tid)
{
    int kend = kbeg + 256;
    {
        int o0s = max(kbeg, 0), o0e = min(kend, l0);
        if (o0e > o0s) stage(act + (o0s - kbeg) * BB, a0 + o0s * BB, (o0e - o0s) * BB, tid);
        int s1s = l0, s1e = l0 + l1;
        int o1s = max(kbeg, s1s), o1e = min(kend, s1e);
        if (l1 && o1e > o1s) stage(act + (o1s - kbeg) * BB, a1 + (o1s - s1s) * BB, (o1e - o1s) * BB, tid);
        int s2s = s1e, s2e = s1e + l2;
        int o2s = max(kbeg, s2s), o2e = min(kend, s2e);
        if (l2 && o2e > o2s) stage(act + (o2s - kbeg) * BB, a2 + (o2s - s2s) * BB, (o2e - o2s) * BB, tid);
    }
    int lrow = tid >> 3, lkh = (tid & 7) * 8;
    issue_chunk(wbufs, wA, strA, lenA, wB, strB, rowbase, kbeg, 0, lrow, lkh);
    int rg = tid >> 2, b4 = (tid & 3) * 4;
    float acc[2][4] = {};
#pragma unroll
    for (int c = 0; c < 4; c++) {
        if (c + 1 < 4) {
            issue_chunk(wbufs, wA, strA, lenA, wB, strB, rowbase, kbeg + (c + 1) * 64, (c + 1) & 1, lrow, lkh);
            cp_wait1();
        } else {
            cp_wait0();
        }
        __syncthreads();
        const __half* wb = wbufs + (c & 1) * (256 * WSTH);
        const float* ac = act + c * 64 * BB;
#pragma unroll 8
        for (int l = 0; l < 64; l += 4) {
            float4 av0 = *(const float4*)&ac[(l + 0) * BB + b4];
            float4 av1 = *(const float4*)&ac[(l + 1) * BB + b4];
            float4 av2 = *(const float4*)&ac[(l + 2) * BB + b4];
            float4 av3 = *(const float4*)&ac[(l + 3) * BB + b4];
#pragma unroll
            for (int m = 0; m < 2; m++) {
                uint2 wr = *(const uint2*)(wb + (rg + (m << 7)) * WSTH + l);
                float2 w01 = __half22float2(*reinterpret_cast<__half2*>(&wr.x));
                float2 w23 = __half22float2(*reinterpret_cast<__half2*>(&wr.y));
                acc[m][0] += w01.x * av0.x + w01.y * av1.x + w23.x * av2.x + w23.y * av3.x;
                acc[m][1] += w01.x * av0.y + w01.y * av1.y + w23.x * av2.y + w23.y * av3.y;
                acc[m][2] += w01.x * av0.z + w01.y * av1.z + w23.x * av2.z + w23.y * av3.z;
                acc[m][3] += w01.x * av0.w + w01.y * av1.w + w23.x * av2.w + w23.y * av3.w;
            }
        }
        __syncthreads();
    }
#pragma unroll
    for (int m = 0; m < 2; m++)
#pragma unroll
        for (int cc = 0; cc < 4; cc++)
            part[(size_t)((slot * BB + b4 + cc) << 12) + rowbase + rg + (m << 7)] = acc[m][cc];
    __syncthreads();
}

__device__ void loc64(int b, int e, const float* __restrict__ lw,
                      const float* __restrict__ ld_, float* sbuf, int tid) {
    float* win = sbuf;
    float* locs = sbuf + 192;
    int t0 = e * 64;
    if (tid < 192) {
        int ch = tid / 96, idx = tid % 96;
        int tt = t0 - 15 + idx;
        bool ok = (idx < 94) && (tt >= 0) && (tt < TENC);
        const float* src = ch ? g_wcum : g_w;
        win[ch * 96 + idx] = ok ? __ldcg(&src[b * TENC + tt]) : 0.f;
    }
    __syncthreads();
    for (int i = tid; i < 2048; i += NTHR) {
        int c = i >> 6, tt = i & 63;
        float acc = 0.f;
#pragma unroll
        for (int ch = 0; ch < 2; ch++)
#pragma unroll
            for (int kk = 0; kk < 31; kk++)
                acc += win[ch * 96 + tt + kk] * lw[c * 62 + ch * 31 + kk];
        locs[c * 64 + tt] = acc;
    }
    __syncthreads();
    int f = tid & 127, tg = tid >> 7;   // tg 0..3
    float ldr[32];
#pragma unroll
    for (int c = 0; c < 32; c++) ldr[c] = ld_[f * 32 + c];
    for (int tt = tg * 16; tt < tg * 16 + 16; tt++) {
        float acc = 0.f;
#pragma unroll
        for (int c = 0; c < 32; c++) acc += locs[c * 64 + tt] * ldr[c];
        g_procloc[((size_t)(b * TENC + t0 + tt)) * ADIM + f] = acc;
    }
    __syncthreads();
}

__device__ void proj_unit2(int t, int v, const float* __restrict__ pw,
                           const float* __restrict__ pb, float* __restrict__ out_mel,
                           float* act, int tid) {
    int r = v * 16 + ((tid >> 4) & 15), b = tid & 15;
    const float* wr = pw + (size_t)r * 1536;
    const float* cx = g_ctx + ((t - 1) & 1) * DENC * BB;
    float acc = 0.f;
    for (int ch = 0; ch < 6; ch++) {
        const float* src = (ch < 4) ? g_hdT + ch * 256 * BB : cx + (ch - 4) * 256 * BB;
        stage(act, src, 256 * BB, tid);
        __syncthreads();
        if (tid < 256) {
            const float* w = wr + ch * 256;
#pragma unroll 8
            for (int k = 0; k < 256; k += 4) {
                float4 wv = *(const float4*)(w + k);
                acc += wv.x * act[(k + 0) * BB + b] + wv.y * act[(k + 1) * BB + b] +
                       wv.z * act[(k + 2) * BB + b] + wv.w * act[(k + 3) * BB + b];
            }
        }
        __syncthreads();
    }
    if (tid < 256) {
        acc += pb[r];
        int flat = (t - 1) * FRAME + r;
        out_mel[(size_t)b * (NMEL * 600) + (flat % NMEL) * 600 + flat / NMEL] = acc;
    }
}

// ---------------- launch 4: persistent megakernel, 512 threads ----------------
__global__ void __launch_bounds__(NTHR) k_mega(
    const int* __restrict__ mlen,
    const float* __restrict__ ab_ih, const float* __restrict__ ab_hh,
    const float* __restrict__ db_ih, const float* __restrict__ db_hh,
    const float* __restrict__ Wq, const float* __restrict__ v_att,
    const float* __restrict__ lconv, const float* __restrict__ ldense,
    const float* __restrict__ proj_w, const float* __restrict__ proj_b,
    float* __restrict__ out_mel, float* __restrict__ out_align)
{
    extern __shared__ float dsm[];
    float* act = dsm;                               // [4096]
    __half* wbufs = (__half*)(dsm + 4096);
    float* sh = dsm;                                // Phase A alias
    __shared__ int sh_u;
    int cta = blockIdx.x, tid = threadIdx.x;
    unsigned ph = 0;

    for (int t = 0; t <= TSTEPS; t++) {
        // =========== Phase A ===========
        if (cta < 16 && t < TSTEPS) {
            int b = cta;
            float* s_ha = sh;                       // [0,1024)
            for (int j = tid; j < ARNN; j += NTHR) {
                float g[4];
#pragma unroll
                for (int gi = 0; gi < 4; gi++) {
                    int row = gi * 1024 + j;
                    float s = ab_ih[row] + ab_hh[row];
#pragma unroll
                    for (int sl = 0; sl < 7; sl++)
                        s += __ldcg(&g_pA[(size_t)((sl * BB + b) << 12) + row]);
                    g[gi] = s;
                }
                float c = sigf(g[1]) * __ldcg(&g_caT[j * BB + b]) + sigf(g[0]) * tanhf(g[2]);
                float h = sigf(g[3]) * tanhf(c);
                g_caT[j * BB + b] = c;
                g_haT[j * BB + b] = h;
                s_ha[j] = h;
            }
            __syncthreads();
            // q = Wq @ h_a, 4-way K split over 512 threads
            {
                int f = tid & 127, q4 = tid >> 7;
                const float* wr = Wq + (size_t)f * ARNN + q4 * 256;
                const float* ha = s_ha + q4 * 256;
                float acc = 0.f;
#pragma unroll 4
                for (int k = 0; k < 256; k += 4) {
                    float4 wv = *(const float4*)(wr + k);
                    acc += wv.x * ha[k] + wv.y * ha[k + 1] + wv.z * ha[k + 2] + wv.w * ha[k + 3];
                }
                sh[1024 + tid] = acc;               // [1024,1536)
            }
            __syncthreads();
            if (tid < 128) {
                sh[1536 + tid] = sh[1024 + tid] + sh[1152 + tid] + sh[1280 + tid] + sh[1408 + tid]; // qv
                sh[1664 + tid] = v_att[tid];        // vs
            }
            __syncthreads();
            // energies: one t per thread
            int L = mlen[b];
            float ev;
            {
                int tt = tid;
                const float* pl = &g_procloc[((size_t)b * TENC + tt) * ADIM];
                const float* pv = &g_pm[((size_t)b * TENC + tt) * ADIM];
                float acc = 0.f;
#pragma unroll 4
                for (int f = 0; f < ADIM; f += 4) {
                    float4 a = __ldcg((const float4*)(pl + f));
                    float4 p = __ldg((const float4*)(pv + f));
                    acc += sh[1664 + f + 0] * tanh_fast(sh[1536 + f + 0] + a.x + p.x);
                    acc += sh[1664 + f + 1] * tanh_fast(sh[1536 + f + 1] + a.y + p.y);
                    acc += sh[1664 + f + 2] * tanh_fast(sh[1536 + f + 2] + a.z + p.z);
                    acc += sh[1664 + f + 3] * tanh_fast(sh[1536 + f + 3] + a.w + p.w);
                }
                ev = (tt >= L) ? -1e9f : acc;
            }
            float* red = sh + 1792;                 // [1792,2304)
            red[tid] = ev;
            __syncthreads();
            for (int s = 256; s > 0; s >>= 1) {
                if (tid < s) red[tid] = fmaxf(red[tid], red[tid + s]);
                __syncthreads();
            }
            float mx = red[0];
            __syncthreads();
            float ex = expf(ev - mx);
            red[tid] = ex;
            __syncthreads();
            for (int s = 256; s > 0; s >>= 1) {
                if (tid < s) red[tid] += red[tid + s];
                __syncthreads();
            }
            float inv = 1.f / red[0];
            {
                float wv = ex * inv;
                g_w[b * TENC + tid] = wv;
                g_wcum[b * TENC + tid] = __ldcg(&g_wcum[b * TENC + tid]) + wv;
                out_align[((size_t)b * TSTEPS + t) * TENC + tid] = wv;
            }
            __syncthreads();
            __threadfence();
            if (tid == 0) *(volatile int*)&g_wflag[b * 32] = t + 1;
        } else if (cta >= 16 && cta < 80 && t < TSTEPS) {
            // ctx helpers: 4 CTAs/b, 128-d slice, 8-way t split
            int v = cta - 16, b = v >> 2, d0 = (v & 3) * 128;
            if (tid == 0) {
                while (*(volatile int*)&g_wflag[b * 32] != t + 1) __nanosleep(32);
            }
            __syncthreads();
            for (int i = tid; i < TENC; i += NTHR) sh[i] = __ldcg(&g_w[b * TENC + i]);
            __syncthreads();
            int dp = (tid & 63) * 2, hf = tid >> 6;   // hf 0..7
            const __half* mb = h_mem + ((size_t)b * TENC + hf * 64) * DENC + d0 + dp;
            float a0 = 0.f, a1 = 0.f;
#pragma unroll 8
            for (int tt = 0; tt < 64; tt++) {
                float2 f2 = __half22float2(__ldg((const __half2*)&mb[(size_t)tt * DENC]));
                float wv = sh[hf * 64 + tt];
                a0 += wv * f2.x;
                a1 += wv * f2.y;
            }
            sh[512 + hf * 128 + dp] = a0;
            sh[512 + hf * 128 + dp + 1] = a1;
            __syncthreads();
            if (tid < 128) {
                float s = 0.f;
#pragma unroll
                for (int hh = 0; hh < 8; hh++) s += sh[512 + hh * 128 + tid];
                g_ctx[(t & 1) * DENC * BB + (d0 + tid) * BB + b] = s;
            }
        } else if (cta >= 80 && cta < 112 && t > 0) {
            // decoder LSTM cell: 2 CTAs/b, 512 j each
            int v = cta - 80, b = v >> 1, j = (v & 1) * 512 + tid;
            float g[4];
#pragma unroll
            for (int gi = 0; gi < 4; gi++) {
                int row = gi * 1024 + j;
                float s = db_ih[row] + db_hh[row];
#pragma unroll
                for (int sl = 0; sl < 10; sl++)
                    s += __ldcg(&g_pD[(size_t)((sl * BB + b) << 12) + row]);
                g[gi] = s;
            }
            float c = sigf(g[1]) * __ldcg(&g_cdT[j * BB + b]) + sigf(g[0]) * tanhf(g[2]);
            float h = sigf(g[3]) * tanhf(c);
            g_cdT[j * BB + b] = c;
            g_hdT[j * BB + b] = h;
        }
        gsync(++ph);
        if (t == TSTEPS) break;

        // =========== Phase B: dynamic work queue ===========
        const float* ctx_t = g_ctx + (t & 1) * DENC * BB;
        for (;;) {
            if (tid == 0) sh_u = (int)atomicAdd(&g_qcnt[t], 1u);
            __syncthreads();
            int u = sh_u;
            __syncthreads();
            if (u >= NUNITS) break;
            if (u < 160) {
                int rc = u / 10, kc = u % 10;
                gate_unit2(act, wbufs,
                           h_dwih, 1536, 1536, h_dwhh, 1024,
                           g_haT, 1024, ctx_t, 512, g_hdT, 1024,
                           g_pD, kc, rc * 256, kc * 256, tid);
            } else if (u < 272) {
                if (t < TSTEPS - 1) {
                    int v = u - 160, rc = v / 7, kc = v % 7;
                    gate_unit2(act, wbufs,
                               h_awih, 768, 768, h_awhh, 1024,
                               g_preT + (size_t)(t + 1) * PRE * BB, 256, ctx_t, 512, g_haT, 1024,
                               g_pA, kc, rc * 256, kc * 256, tid);
                }
            } else if (u < 400) {
                if (t < TSTEPS - 1) {
                    int v = u - 272;
                    loc64(v >> 3, v & 7, lconv, ldense, act, tid);
                }
            } else {
                if (t > 0) proj_unit2(t, u - 400, proj_w, proj_b, out_mel, act, tid);
            }
        }
        gsync(++ph);
    }

    if (cta < 15) proj_unit2(TSTEPS, cta, proj_w, proj_b, out_mel, act, tid);
}

extern "C" void kernel_launch(void* const* d_in, const int* in_sizes, int n_in,
                              void* d_out, int out_size) {
    const float* memory = (const float*)d_in[0];
    const float* dec_in = (const float*)d_in[1];
    const int*   mlen   = (const int*)d_in[2];
    const float* pw1    = (const float*)d_in[3];
    const float* pw2    = (const float*)d_in[4];
    const float* aw_ih  = (const float*)d_in[5];
    const float* aw_hh  = (const float*)d_in[6];
    const float* ab_ih  = (const float*)d_in[7];
    const float* ab_hh  = (const float*)d_in[8];
    const float* dw_ih  = (const float*)d_in[9];
    const float* dw_hh  = (const float*)d_in[10];
    const float* db_ih  = (const float*)d_in[11];
    const float* db_hh  = (const float*)d_in[12];
    const float* Wq     = (const float*)d_in[13];
    const float* Wm     = (const float*)d_in[14];
    const float* v_att  = (const float*)d_in[15];
    const float* lconv  = (const float*)d_in[16];
    const float* ldense = (const float*)d_in[17];
    const float* proj_w = (const float*)d_in[18];
    const float* proj_b = (const float*)d_in[19];

    float* out = (float*)d_out;
    float* align_out = out + (size_t)BB * NMEL * 600;

    float *s_xraw, *s_h1;
    cudaGetSymbolAddress((void**)&s_xraw, g_xraw);
    cudaGetSymbolAddress((void**)&s_h1, g_h1);

    static int smem_set = 0;
    int smem_bytes = SMEM_FLOATS * 4;
    if (!smem_set) {
        cudaFuncSetAttribute(k_mega, cudaFuncAttributeMaxDynamicSharedMemorySize, smem_bytes);
        smem_set = 1;
    }

    k_prep<<<2048, 256>>>(dec_in, aw_ih, aw_hh, dw_ih, dw_hh, memory);
    k_sgemm<<<dim3(50, 4), 256>>>(s_xraw, pw1, s_h1, NFRAMES * BB, PRE, FRAME, 1, 0);
    k_sgemm2<<<456, 256>>>(pw2, memory, Wm);
    k_mega<<<GRID, NTHR, smem_bytes>>>(mlen,
                           ab_ih, ab_hh, db_ih, db_hh,
                           Wq, v_att, lconv, ldense, proj_w, proj_b,
                           out, align_out);
}

// round 14
// speedup vs baseline: 1.3041x; 1.2696x over previous
#include <cuda_runtime.h>
#include <cuda_fp16.h>
#include <math.h>

#define BB 16
#define TENC 512
#define DENC 512
#define NMEL 80
#define FRAME 240
#define TSTEPS 200
#define NFRAMES 199
#define PRE 256
#define ARNN 1024
#define ADIM 128
#define GRID 148
#define NTHR 512
#define NUNITS 415
#define WSTH 72
#define AHST 264
#define SMEM_FLOATS (4096 + (2 * 256 * WSTH) / 2 + (16 * AHST) / 2)

__device__ float g_xraw[NFRAMES * BB * FRAME];
__device__ float g_h1[NFRAMES * BB * PRE];
__device__ float g_preT[TSTEPS * PRE * BB];     // [t][f][b]
__device__ float g_pm[BB * TENC * ADIM];
__device__ float g_procloc[BB * TENC * ADIM];
__device__ float g_haT[ARNN * BB];              // [j][b]
__device__ float g_caT[ARNN * BB];
__device__ float g_hdT[ARNN * BB];
__device__ float g_cdT[ARNN * BB];
__device__ float g_ctx[2 * DENC * BB];          // [parity][d][b]
__device__ float g_w[BB * TENC];
__device__ float g_wcum[BB * TENC];
__device__ float g_pA[8 * BB * 4096];           // [slot][b][row]
__device__ float g_pD[10 * BB * 4096];
__device__ int   g_wflag[BB * 32];
__device__ unsigned g_qcnt[TSTEPS];
__device__ __align__(128) unsigned g_barA[32];
__device__ __align__(128) unsigned g_barB[32];

__device__ __align__(16) __half h_awih[4096 * 768];
__device__ __align__(16) __half h_awhh[4096 * 1024];
__device__ __align__(16) __half h_dwih[4096 * 1536];
__device__ __align__(16) __half h_dwhh[4096 * 1024];
__device__ __align__(16) __half h_mem[BB * TENC * DENC];

__device__ __forceinline__ float sigf(float x) { return 1.f / (1.f + expf(-x)); }
__device__ __forceinline__ float tanh_fast(float x) {
    float y; asm("tanh.approx.f32 %0, %1;" : "=f"(y) : "f"(x)); return y;
}

__device__ __forceinline__ void cp16cg(__half* s, const __half* g) {
    unsigned ss = (unsigned)__cvta_generic_to_shared(s);
    asm volatile("cp.async.cg.shared.global [%0], [%1], 16;" :: "r"(ss), "l"(g));
}
__device__ __forceinline__ void cp_commit() { asm volatile("cp.async.commit_group;"); }
__device__ __forceinline__ void cp_wait0() { asm volatile("cp.async.wait_group 0;"); }
__device__ __forceinline__ void cp_wait1() { asm volatile("cp.async.wait_group 1;"); }

__device__ __forceinline__ void mma16816(float* c, unsigned a0, unsigned a1, unsigned a2, unsigned a3,
                                         unsigned b0, unsigned b1) {
    asm volatile("mma.sync.aligned.m16n8k16.row.col.f32.f16.f16.f32 "
                 "{%0,%1,%2,%3}, {%4,%5,%6,%7}, {%8,%9}, {%0,%1,%2,%3};"
                 : "+f"(c[0]), "+f"(c[1]), "+f"(c[2]), "+f"(c[3])
                 : "r"(a0), "r"(a1), "r"(a2), "r"(a3), "r"(b0), "r"(b1));
}

__device__ __forceinline__ void gsync(unsigned ph) {
    __threadfence();
    __syncthreads();
    if (threadIdx.x == 0) {
        if (atomicAdd(&g_barA[0], 1u) == GRID - 1) {
            g_barA[0] = 0;
            __threadfence();
            *(volatile unsigned*)&g_barB[0] = ph;
        } else {
            while (*(volatile unsigned*)&g_barB[0] != ph) __nanosleep(32);
            __threadfence();
        }
    }
    __syncthreads();
}

// ---------------- launch 1: init + gather + fp16 conversions ----------------
__global__ void k_prep(const float* __restrict__ din,
                       const float* __restrict__ aw_ih, const float* __restrict__ aw_hh,
                       const float* __restrict__ dw_ih, const float* __restrict__ dw_hh,
                       const float* __restrict__ memory) {
    int i0 = blockIdx.x * 256 + threadIdx.x;
    int st = gridDim.x * 256;
    if (i0 == 0) { g_barA[0] = 0; g_barB[0] = 0; }
    for (int k = i0; k < TSTEPS; k += st) g_qcnt[k] = 0;
    for (int k = i0; k < ARNN * BB; k += st) { g_haT[k]=0.f; g_caT[k]=0.f; g_hdT[k]=0.f; g_cdT[k]=0.f; }
    for (int k = i0; k < 2 * DENC * BB; k += st) g_ctx[k] = 0.f;
    for (int k = i0; k < BB * TENC; k += st) { g_w[k] = 0.f; g_wcum[k] = 0.f; }
    for (int k = i0; k < PRE * BB; k += st) g_preT[k] = 0.f;
    for (int k = i0; k < BB * 32; k += st) g_wflag[k] = 0;
    for (int k = i0; k < 8 * BB * 4096; k += st) g_pA[k] = 0.f;
    for (int k = i0; k < BB * TENC * ADIM; k += st) g_procloc[k] = 0.f;
    for (int idx = i0; idx < NFRAMES * BB * FRAME; idx += st) {
        int j = idx % FRAME, m = idx / FRAME;
        int b = m % BB, d = m / BB;
        int flat = d * FRAME + j;
        g_xraw[idx] = din[(b * NMEL + flat % NMEL) * 600 + flat / NMEL];
    }
    for (int k = i0; k < 4096 * 768; k += st) h_awih[k] = __float2half(aw_ih[k]);
    for (int k = i0; k < 4096 * 1024; k += st) h_awhh[k] = __float2half(aw_hh[k]);
    for (int k = i0; k < 4096 * 1536; k += st) h_dwih[k] = __float2half(dw_ih[k]);
    for (int k = i0; k < 4096 * 1024; k += st) h_dwhh[k] = __float2half(dw_hh[k]);
    for (int k = i0; k < BB * TENC * DENC; k += st) h_mem[k] = __float2half(memory[k]);
}

// ---------------- prologue SGEMM ----------------
__device__ void sgemm_tile(float* As, float* Bs,
                           const float* __restrict__ A, const float* __restrict__ Bw,
                           float* __restrict__ C, int M, int N, int K, int relu, int mode,
                           int m0, int n0) {
    int tx = threadIdx.x, tr = tx >> 4, tc = tx & 15;
    float acc[4][4] = {};
    for (int k0 = 0; k0 < K; k0 += 16) {
        for (int i = tx; i < 1024; i += 256) {
            int mm = i >> 4, kk = i & 15;
            int m = m0 + mm, k = k0 + kk;
            As[kk * 68 + mm] = (m < M) ? A[(size_t)m * K + k] : 0.f;
            int n = n0 + mm;
            Bs[kk * 68 + mm] = (n < N) ? Bw[(size_t)n * K + k] : 0.f;
        }
        __syncthreads();
#pragma unroll
        for (int kk = 0; kk < 16; kk++) {
            float4 a4 = *(const float4*)&As[kk * 68 + tr * 4];
            float4 b4 = *(const float4*)&Bs[kk * 68 + tc * 4];
            float a_[4] = {a4.x, a4.y, a4.z, a4.w};
            float b_[4] = {b4.x, b4.y, b4.z, b4.w};
#pragma unroll
            for (int r = 0; r < 4; r++)
#pragma unroll
                for (int c = 0; c < 4; c++) acc[r][c] += a_[r] * b_[c];
        }
        __syncthreads();
    }
    for (int r = 0; r < 4; r++)
        for (int c = 0; c < 4; c++) {
            int m = m0 + tr * 4 + r, n = n0 + tc * 4 + c;
            if (m < M && n < N) {
                float v = acc[r][c];
                if (relu) v = fmaxf(v, 0.f);
                if (mode == 0) C[(size_t)m * N + n] = v;
                else C[(((m >> 4) + 1) * PRE + n) * BB + (m & 15)] = v;
            }
        }
}

__global__ void k_sgemm(const float* __restrict__ A, const float* __restrict__ Bw,
                        float* __restrict__ C, int M, int N, int K, int relu, int mode) {
    __shared__ float As[16 * 68];
    __shared__ float Bs[16 * 68];
    sgemm_tile(As, Bs, A, Bw, C, M, N, K, relu, mode, blockIdx.x * 64, blockIdx.y * 64);
}

__global__ void k_sgemm2(const float* __restrict__ pw2, const float* __restrict__ memory,
                         const float* __restrict__ Wm) {
    __shared__ float As[16 * 68];
    __shared__ float Bs[16 * 68];
    if (blockIdx.x < 200) {
        int bx = blockIdx.x % 50, by = blockIdx.x / 50;
        sgemm_tile(As, Bs, g_h1, pw2, g_preT, NFRAMES * BB, PRE, PRE, 1, 1, bx * 64, by * 64);
    } else {
        int v = blockIdx.x - 200;
        int bx = v % 128, by = v / 128;
        sgemm_tile(As, Bs, memory, Wm, g_pm, BB * TENC, ADIM, DENC, 0, 0, bx * 64, by * 64);
    }
}

__device__ __forceinline__ void stage(float* dst, const float* src, int nfloats, int tid) {
    const float4* s4 = (const float4*)src;
    float4* d4 = (float4*)dst;
    int n4 = nfloats >> 2;
    for (int i = tid; i < n4; i += NTHR) d4[i] = __ldcg(s4 + i);
}

__device__ __forceinline__ void issue_chunk(__half* wbufs, const __half* wA, int strA, int lenA,
        const __half* wB, int strB, int rowbase, int kg, int buf, int lrow, int lkh) {
    const __half* ws; int wst; int ko;
    if (kg < lenA) { ws = wA; wst = strA; ko = kg; } else { ws = wB; wst = strB; ko = kg - lenA; }
    __half* dst = wbufs + buf * (256 * WSTH);
#pragma unroll
    for (int i = 0; i < 4; i++) {
        int row = lrow + i * 64;
        cp16cg(dst + row * WSTH + lkh, ws + (size_t)(rowbase + row) * wst + ko + lkh);
    }
    cp_commit();
}

// ---- tensor-core gate unit: 16 warps x (16 rows x 16 b x 256 K) via mma.m16n8k16 ----
__device__ void gate_mma(__half* act_h, __half* wbufs,
    const __half* wA, int strA, int lenA, const __half* wB, int strB,
    const float* a0, int l0, const float* a1, int l1, const float* a2, int l2,
    float* part, int slot, int rowbase, int kbeg, int tid)
{
    // stage activations fp32 [k][16] -> fp16 act_h[b][kk] (kk = k - kbeg, 0..255)
    {
        int kk = tid >> 1, bh = (tid & 1) * 8;
        int kg = kbeg + kk;
        const float* src;
        if (kg < l0) src = a0 + (size_t)kg * BB;
        else if (kg < l0 + l1) src = a1 + (size_t)(kg - l0) * BB;
        else src = a2 + (size_t)(kg - l0 - l1) * BB;
        float4 f0 = __ldcg((const float4*)(src + bh));
        float4 f1 = __ldcg((const float4*)(src + bh + 4));
        act_h[(bh + 0) * AHST + kk] = __float2half(f0.x);
        act_h[(bh + 1) * AHST + kk] = __float2half(f0.y);
        act_h[(bh + 2) * AHST + kk] = __float2half(f0.z);
        act_h[(bh + 3) * AHST + kk] = __float2half(f0.w);
        act_h[(bh + 4) * AHST + kk] = __float2half(f1.x);
        act_h[(bh + 5) * AHST + kk] = __float2half(f1.y);
        act_h[(bh + 6) * AHST + kk] = __float2half(f1.z);
        act_h[(bh + 7) * AHST + kk] = __float2half(f1.w);
    }
    int lrow = tid >> 3, lkh = (tid & 7) * 8;
    issue_chunk(wbufs, wA, strA, lenA, wB, strB, rowbase, kbeg, 0, lrow, lkh);
    int w = tid >> 5, lane = tid & 31, grp = lane >> 2, qp = lane & 3;
    int r0 = w * 16;
    float cfr[2][4] = {};
#pragma unroll
    for (int c = 0; c < 4; c++) {
        if (c + 1 < 4) {
            issue_chunk(wbufs, wA, strA, lenA, wB, strB, rowbase, kbeg + (c + 1) * 64, (c + 1) & 1, lrow, lkh);
            cp_wait1();
        } else {
            cp_wait0();
        }
        __syncthreads();
        const __half* wb = wbufs + (c & 1) * (256 * WSTH);
#pragma unroll
        for (int ks = 0; ks < 4; ks++) {
            int kc = ks * 16;           // k offset within chunk
            int kk0 = c * 64 + kc;      // k offset within act_h
            unsigned a0r = *(const unsigned*)&wb[(r0 + grp) * WSTH + kc + qp * 2];
            unsigned a1r = *(const unsigned*)&wb[(r0 + grp + 8) * WSTH + kc + qp * 2];
            unsigned a2r = *(const unsigned*)&wb[(r0 + grp) * WSTH + kc + qp * 2 + 8];
            unsigned a3r = *(const unsigned*)&wb[(r0 + grp + 8) * WSTH + kc + qp * 2 + 8];
            unsigned b0r = *(const unsigned*)&act_h[grp * AHST + kk0 + qp * 2];
            unsigned b1r = *(const unsigned*)&act_h[grp * AHST + kk0 + qp * 2 + 8];
            unsigned b2r = *(const unsigned*)&act_h[(grp + 8) * AHST + kk0 + qp * 2];
            unsigned b3r = *(const unsigned*)&act_h[(grp + 8) * AHST + kk0 + qp * 2 + 8];
            mma16816(cfr[0], a0r, a1r, a2r, a3r, b0r, b1r);
            mma16816(cfr[1], a0r, a1r, a2r, a3r, b2r, b3r);
        }
        __syncthreads();
    }
    // store C: cfr[h] covers b = h*8 + qp*2 (+1), rows grp / grp+8
#pragma unroll
    for (int h = 0; h < 2; h++) {
        int bb = h * 8 + qp * 2;
        size_t base0 = (size_t)((slot * BB + bb) << 12) + rowbase + r0;
        size_t base1 = (size_t)((slot * BB + bb + 1) << 12) + rowbase + r0;
        part[base0 + grp] = cfr[h][0];
        part[base1 + grp] = cfr[h][1];
        part[base0 + grp + 8] = cfr[h][2];
        part[base1 + grp + 8] = cfr[h][3];
    }
    __syncthreads();
}

__device__ void loc64(int b, int e, const float* __restrict__ lw,
                      const float* __restrict__ ld_, float* sbuf, int tid) {
    float* win = sbuf;
    float* locs = sbuf + 192;
    int t0 = e * 64;
    if (tid < 192) {
        int ch = tid / 96, idx = tid % 96;
        int tt = t0 - 15 + idx;
        bool ok = (idx < 94) && (tt >= 0) && (tt < TENC);
        const float* src = ch ? g_wcum : g_w;
        win[ch * 96 + idx] = ok ? __ldcg(&src[b * TENC + tt]) : 0.f;
    }
    __syncthreads();
    for (int i = tid; i < 2048; i += NTHR) {
        int c = i >> 6, tt = i & 63;
        float acc = 0.f;
#pragma unroll
        for (int ch = 0; ch < 2; ch++)
#pragma unroll
            for (int kk = 0; kk < 31; kk++)
                acc += win[ch * 96 + tt + kk] * lw[c * 62 + ch * 31 + kk];
        locs[c * 64 + tt] = acc;
    }
    __syncthreads();
    int f = tid & 127, tg = tid >> 7;
    float ldr[32];
#pragma unroll
    for (int c = 0; c < 32; c++) ldr[c] = ld_[f * 32 + c];
    for (int tt = tg * 16; tt < tg * 16 + 16; tt++) {
        float acc = 0.f;
#pragma unroll
        for (int c = 0; c < 32; c++) acc += locs[c * 64 + tt] * ldr[c];
        g_procloc[((size_t)(b * TENC + t0 + tt)) * ADIM + f] = acc;
    }
    __syncthreads();
}

__device__ void proj_unit2(int t, int v, const float* __restrict__ pw,
                           const float* __restrict__ pb, float* __restrict__ out_mel,
                           float* act, int tid) {
    int r = v * 16 + ((tid >> 4) & 15), b = tid & 15;
    const float* wr = pw + (size_t)r * 1536;
    const float* cx = g_ctx + ((t - 1) & 1) * DENC * BB;
    float acc = 0.f;
    for (int ch = 0; ch < 6; ch++) {
        const float* src = (ch < 4) ? g_hdT + ch * 256 * BB : cx + (ch - 4) * 256 * BB;
        stage(act, src, 256 * BB, tid);
        __syncthreads();
        if (tid < 256) {
            const float* w = wr + ch * 256;
#pragma unroll 8
            for (int k = 0; k < 256; k += 4) {
                float4 wv = *(const float4*)(w + k);
                acc += wv.x * act[(k + 0) * BB + b] + wv.y * act[(k + 1) * BB + b] +
                       wv.z * act[(k + 2) * BB + b] + wv.w * act[(k + 3) * BB + b];
            }
        }
        __syncthreads();
    }
    if (tid < 256) {
        acc += pb[r];
        int flat = (t - 1) * FRAME + r;
        out_mel[(size_t)b * (NMEL * 600) + (flat % NMEL) * 600 + flat / NMEL] = acc;
    }
}

// ---------------- launch 4: persistent megakernel ----------------
__global__ void __launch_bounds__(NTHR) k_mega(
    const int* __restrict__ mlen,
    const float* __restrict__ ab_ih, const float* __restrict__ ab_hh,
    const float* __restrict__ db_ih, const float* __restrict__ db_hh,
    const float* __restrict__ Wq, const float* __restrict__ v_att,
    const float* __restrict__ lconv, const float* __restrict__ ldense,
    const float* __restrict__ proj_w, const float* __restrict__ proj_b,
    float* __restrict__ out_mel, float* __restrict__ out_align)
{
    extern __shared__ float dsm[];
    float* act = dsm;                               // [4096] fp32 scratch (loc/proj/PhaseA)
    __half* wbufs = (__half*)(dsm + 4096);          // [2][256*WSTH]
    __half* act_h = (__half*)(dsm + 4096 + (2 * 256 * WSTH) / 2);  // [16][AHST]
    float* sh = dsm;
    __shared__ int sh_u;
    int cta = blockIdx.x, tid = threadIdx.x;
    unsigned ph = 0;

    for (int t = 0; t <= TSTEPS; t++) {
        // =========== Phase A ===========
        if (cta < 16 && t < TSTEPS) {
            int b = cta;
            float* s_ha = sh;
            for (int j = tid; j < ARNN; j += NTHR) {
                float g[4];
#pragma unroll
                for (int gi = 0; gi < 4; gi++) {
                    int row = gi * 1024 + j;
                    float s = ab_ih[row] + ab_hh[row];
#pragma unroll
                    for (int sl = 0; sl < 7; sl++)
                        s += __ldcg(&g_pA[(size_t)((sl * BB + b) << 12) + row]);
                    g[gi] = s;
                }
                float c = sigf(g[1]) * __ldcg(&g_caT[j * BB + b]) + sigf(g[0]) * tanhf(g[2]);
                float h = sigf(g[3]) * tanhf(c);
                g_caT[j * BB + b] = c;
                g_haT[j * BB + b] = h;
                s_ha[j] = h;
            }
            __syncthreads();
            {
                int f = tid & 127, q4 = tid >> 7;
                const float* wr = Wq + (size_t)f * ARNN + q4 * 256;
                const float* ha = s_ha + q4 * 256;
                float acc = 0.f;
#pragma unroll 4
                for (int k = 0; k < 256; k += 4) {
                    float4 wv = *(const float4*)(wr + k);
                    acc += wv.x * ha[k] + wv.y * ha[k + 1] + wv.z * ha[k + 2] + wv.w * ha[k + 3];
                }
                sh[1024 + tid] = acc;
            }
            __syncthreads();
            if (tid < 128) {
                sh[1536 + tid] = sh[1024 + tid] + sh[1152 + tid] + sh[1280 + tid] + sh[1408 + tid];
                sh[1664 + tid] = v_att[tid];
            }
            __syncthreads();
            int L = mlen[b];
            float ev;
            {
                int tt = tid;
                const float* pl = &g_procloc[((size_t)b * TENC + tt) * ADIM];
                const float* pv = &g_pm[((size_t)b * TENC + tt) * ADIM];
                float acc = 0.f;
#pragma unroll 4
                for (int f = 0; f < ADIM; f += 4) {
                    float4 a = __ldcg((const float4*)(pl + f));
                    float4 p = __ldg((const float4*)(pv + f));
                    acc += sh[1664 + f + 0] * tanh_fast(sh[1536 + f + 0] + a.x + p.x);
                    acc += sh[1664 + f + 1] * tanh_fast(sh[1536 + f + 1] + a.y + p.y);
                    acc += sh[1664 + f + 2] * tanh_fast(sh[1536 + f + 2] + a.z + p.z);
                    acc += sh[1664 + f + 3] * tanh_fast(sh[1536 + f + 3] + a.w + p.w);
                }
                ev = (tt >= L) ? -1e9f : acc;
            }
            float* red = sh + 1792;
            red[tid] = ev;
            __syncthreads();
            for (int s = 256; s > 0; s >>= 1) {
                if (tid < s) red[tid] = fmaxf(red[tid], red[tid + s]);
                __syncthreads();
            }
            float mx = red[0];
            __syncthreads();
            float ex = expf(ev - mx);
            red[tid] = ex;
            __syncthreads();
            for (int s = 256; s > 0; s >>= 1) {
                if (tid < s) red[tid] += red[tid + s];
                __syncthreads();
            }
            float inv = 1.f / red[0];
            {
                float wv = ex * inv;
                g_w[b * TENC + tid] = wv;
                g_wcum[b * TENC + tid] = __ldcg(&g_wcum[b * TENC + tid]) + wv;
                out_align[((size_t)b * TSTEPS + t) * TENC + tid] = wv;
            }
            __syncthreads();
            __threadfence();
            if (tid == 0) *(volatile int*)&g_wflag[b * 32] = t + 1;
        } else if (cta >= 16 && cta < 80 && t < TSTEPS) {
            int v = cta - 16, b = v >> 2, d0 = (v & 3) * 128;
            if (tid == 0) {
                while (*(volatile int*)&g_wflag[b * 32] != t + 1) __nanosleep(32);
            }
            __syncthreads();
            for (int i = tid; i < TENC; i += NTHR) sh[i] = __ldcg(&g_w[b * TENC + i]);
            __syncthreads();
            int dp = (tid & 63) * 2, hf = tid >> 6;
            const __half* mb = h_mem + ((size_t)b * TENC + hf * 64) * DENC + d0 + dp;
            float a0 = 0.f, a1 = 0.f;
#pragma unroll 8
            for (int tt = 0; tt < 64; tt++) {
                float2 f2 = __half22float2(__ldg((const __half2*)&mb[(size_t)tt * DENC]));
                float wv = sh[hf * 64 + tt];
                a0 += wv * f2.x;
                a1 += wv * f2.y;
            }
            sh[512 + hf * 128 + dp] = a0;
            sh[512 + hf * 128 + dp + 1] = a1;
            __syncthreads();
            if (tid < 128) {
                float s = 0.f;
#pragma unroll
                for (int hh = 0; hh < 8; hh++) s += sh[512 + hh * 128 + tid];
                g_ctx[(t & 1) * DENC * BB + (d0 + tid) * BB + b] = s;
            }
        } else if (cta >= 80 && cta < 112 && t > 0) {
            int v = cta - 80, b = v >> 1, j = (v & 1) * 512 + tid;
            float g[4];
#pragma unroll
            for (int gi = 0; gi < 4; gi++) {
                int row = gi * 1024 + j;
                float s = db_ih[row] + db_hh[row];
#pragma unroll
                for (int sl = 0; sl < 10; sl++)
                    s += __ldcg(&g_pD[(size_t)((sl * BB + b) << 12) + row]);
                g[gi] = s;
            }
            float c = sigf(g[1]) * __ldcg(&g_cdT[j * BB + b]) + sigf(g[0]) * tanhf(g[2]);
            float h = sigf(g[3]) * tanhf(c);
            g_cdT[j * BB + b] = c;
            g_hdT[j * BB + b] = h;
        }
        gsync(++ph);
        if (t == TSTEPS) break;

        // =========== Phase B: dynamic work queue (gate GEMMs on tensor cores) ===========
        const float* ctx_t = g_ctx + (t & 1) * DENC * BB;
        for (;;) {
            if (tid == 0) sh_u = (int)atomicAdd(&g_qcnt[t], 1u);
            __syncthreads();
            int u = sh_u;
            __syncthreads();
            if (u >= NUNITS) break;
            if (u < 160) {
                int rc = u / 10, kc = u % 10;
                gate_mma(act_h, wbufs,
                         h_dwih, 1536, 1536, h_dwhh, 1024,
                         g_haT, 1024, ctx_t, 512, g_hdT, 1024,
                         g_pD, kc, rc * 256, kc * 256, tid);
            } else if (u < 272) {
                if (t < TSTEPS - 1) {
                    int v = u - 160, rc = v / 7, kc = v % 7;
                    gate_mma(act_h, wbufs,
                             h_awih, 768, 768, h_awhh, 1024,
                             g_preT + (size_t)(t + 1) * PRE * BB, 256, ctx_t, 512, g_haT, 1024,
                             g_pA, kc, rc * 256, kc * 256, tid);
                }
            } else if (u < 400) {
                if (t < TSTEPS - 1) {
                    int v = u - 272;
                    loc64(v >> 3, v & 7, lconv, ldense, act, tid);
                }
            } else {
                if (t > 0) proj_unit2(t, u - 400, proj_w, proj_b, out_mel, act, tid);
            }
        }
        gsync(++ph);
    }

    if (cta < 15) proj_unit2(TSTEPS, cta, proj_w, proj_b, out_mel, act, tid);
}

extern "C" void kernel_launch(void* const* d_in, const int* in_sizes, int n_in,
                              void* d_out, int out_size) {
    const float* memory = (const float*)d_in[0];
    const float* dec_in = (const float*)d_in[1];
    const int*   mlen   = (const int*)d_in[2];
    const float* pw1    = (const float*)d_in[3];
    const float* pw2    = (const float*)d_in[4];
    const float* aw_ih  = (const float*)d_in[5];
    const float* aw_hh  = (const float*)d_in[6];
    const float* ab_ih  = (const float*)d_in[7];
    const float* ab_hh  = (const float*)d_in[8];
    const float* dw_ih  = (const float*)d_in[9];
    const float* dw_hh  = (const float*)d_in[10];
    const float* db_ih  = (const float*)d_in[11];
    const float* db_hh  = (const float*)d_in[12];
    const float* Wq     = (const float*)d_in[13];
    const float* Wm     = (const float*)d_in[14];
    const float* v_att  = (const float*)d_in[15];
    const float* lconv  = (const float*)d_in[16];
    const float* ldense = (const float*)d_in[17];
    const float* proj_w = (const float*)d_in[18];
    const float* proj_b = (const float*)d_in[19];

    float* out = (float*)d_out;
    float* align_out = out + (size_t)BB * NMEL * 600;

    float *s_xraw, *s_h1;
    cudaGetSymbolAddress((void**)&s_xraw, g_xraw);
    cudaGetSymbolAddress((void**)&s_h1, g_h1);

    static int smem_set = 0;
    int smem_bytes = SMEM_FLOATS * 4;
    if (!smem_set) {
        cudaFuncSetAttribute(k_mega, cudaFuncAttributeMaxDynamicSharedMemorySize, smem_bytes);
        smem_set = 1;
    }

    k_prep<<<2048, 256>>>(dec_in, aw_ih, aw_hh, dw_ih, dw_hh, memory);
    k_sgemm<<<dim3(50, 4), 256>>>(s_xraw, pw1, s_h1, NFRAMES * BB, PRE, FRAME, 1, 0);
    k_sgemm2<<<456, 256>>>(pw2, memory, Wm);
    k_mega<<<GRID, NTHR, smem_bytes>>>(mlen,
                           ab_ih, ab_hh, db_ih, db_hh,
                           Wq, v_att, lconv, ldense, proj_w, proj_b,
                           out, align_out);
}